// round 11
// baseline (speedup 1.0000x reference)
#include <cuda_runtime.h>
#include <math.h>

#define HH   256
#define LL   5
#define TT   1000
#define BB   128

typedef unsigned long long ull;

// Cross-layer mailboxes: one 8-byte {tag=t+1, value} slot per (layer, batch, t).
// Written exactly once per launch; tags zeroed by reset_mbox_kernel, which runs
// at the END of each launch sequence (device globals start zeroed, so every
// launch — including the first — begins with clean tags).
__device__ ull   g_mbox[LL - 1][BB][TT];   // 4.096 MB
__device__ float g_hseq[BB][TT];           // layer-4 outputs, 512 KB

__device__ __forceinline__ float tanhapx(float x) {
    float r;
    asm("tanh.approx.f32 %0, %1;" : "=f"(r) : "f"(x));
    return r;
}

__device__ __forceinline__ int redux_s32(int v) {
    int r;
    asm volatile("redux.sync.add.s32 %0, %1, 0xffffffff;" : "=r"(r) : "r"(v));
    return r;
}

// ---------------------------------------------------------------- reset
__global__ void reset_mbox_kernel() {
    ull* p = &g_mbox[0][0][0];
    const int n = (LL - 1) * BB * TT;
    for (int i = blockIdx.x * blockDim.x + threadIdx.x; i < n;
         i += gridDim.x * blockDim.x)
        p[i] = 0ull;
}

// ---------------------------------------------------------------- LSTM pipeline
// grid = LL*BB blocks of 128 threads; block (l, b) runs layer l of batch b.
// Each thread owns 2 hidden channels (h = tid, tid+128).
//
// ONLY change vs the previous round: mailbox lookahead deepened from 1 to 3
// slots (register ring p1,p2,p3). The first poll of slot t+3 is issued at
// step t, ~3 cadences before consumption, so the L2 store->load visibility
// latency between layers is off the per-step critical path for any block
// placement. Stale early polls are caught by the tag check and re-polled.
__global__ void __launch_bounds__(128)
lstm_layer_kernel(const float* __restrict__ x,
                  const float* __restrict__ Wih,
                  const float* __restrict__ Whh,
                  const float* __restrict__ bih,
                  const float* __restrict__ bhh,
                  const float* __restrict__ Whr)
{
    __shared__ __align__(16) float xbuf[TT];
    __shared__ __align__(16) int   part[2][4];   // [t&1][warp]

    const int tid  = threadIdx.x;
    const int l    = blockIdx.x >> 7;      // layer
    const int b    = blockIdx.x & 127;     // batch element
    const int w    = tid >> 5;             // warp in block (0..3)
    const int lane = tid & 31;

    // ---- per-thread weights: 2 channels x 4 gates ----
    // gate order i,f,g,o; sigmoid(x)=0.5*tanh(0.5x)+0.5 with 0.5 folded in.
    float wI[2][4], wH[2][4], bS[2][4], wR[2];
#pragma unroll
    for (int ch = 0; ch < 2; ++ch) {
        int h = tid + ch * 128;
#pragma unroll
        for (int g = 0; g < 4; ++g) {
            int idx = l * 1024 + g * 256 + h;
            float s = (g == 2) ? 1.0f : 0.5f;
            wI[ch][g] = Wih[idx] * s;
            wH[ch][g] = Whh[idx] * s;
            bS[ch][g] = (bih[idx] + bhh[idx]) * s;
        }
        wR[ch] = Whr[l * 256 + h];
    }

    if (l == 0) {
        for (int k = tid; k < TT; k += 128)
            xbuf[k] = x[b * TT + k];
    }
    __syncthreads();

    const ull* mb_in  = (l > 0) ? g_mbox[l - 1][b] : (const ull*)0;
    ull*       mb_out = (l < LL - 1) ? g_mbox[l][b] : (ull*)0;

    float c0 = 0.0f, c1 = 0.0f;
    float hp = 0.0f;

    // input prefetch state: 3-deep lookahead ring (issue early, check at use)
    float xin = 0.0f;
    ull p1 = 0ull, p2 = 0ull, p3 = 0ull;
    if (l == 0) {
        xin = xbuf[0];
    } else {
        p1 = *(volatile const ull*)(mb_in + 0);
        p2 = *(volatile const ull*)(mb_in + 1);
        p3 = *(volatile const ull*)(mb_in + 2);
    }

    for (int t = 0; t < TT; ++t) {
        // ---- consume input: verify prefetched tag, re-poll only if stale ----
        float in;
        if (l == 0) {
            in = xin;
            if (t + 1 < TT) xin = xbuf[t + 1];
        } else {
            ull v = p1;
            const unsigned want = (unsigned)(t + 1);
            while ((unsigned)(v >> 32) != want)
                v = *(volatile const ull*)(mb_in + t);
            in = __uint_as_float((unsigned)v);
            // shift the ring; issue the poll for slot t+3 (3 steps early)
            p1 = p2;
            p2 = p3;
            if (t + 3 < TT)
                p3 = *(volatile const ull*)(mb_in + t + 3);
        }

        // ---- two channels of the LSTM cell (f32) ----
        float acc;
        {   // channel 0
            float gi = fmaf(in, wI[0][0], fmaf(hp, wH[0][0], bS[0][0]));
            float gf = fmaf(in, wI[0][1], fmaf(hp, wH[0][1], bS[0][1]));
            float gg = fmaf(in, wI[0][2], fmaf(hp, wH[0][2], bS[0][2]));
            float go = fmaf(in, wI[0][3], fmaf(hp, wH[0][3], bS[0][3]));
            float i_ = fmaf(tanhapx(gi), 0.5f, 0.5f);
            float f_ = fmaf(tanhapx(gf), 0.5f, 0.5f);
            float g_ = tanhapx(gg);
            float o_ = fmaf(tanhapx(go), 0.5f, 0.5f);
            c0 = fmaf(f_, c0, i_ * g_);
            acc = (o_ * tanhapx(c0)) * wR[0];
        }
        {   // channel 1
            float gi = fmaf(in, wI[1][0], fmaf(hp, wH[1][0], bS[1][0]));
            float gf = fmaf(in, wI[1][1], fmaf(hp, wH[1][1], bS[1][1]));
            float gg = fmaf(in, wI[1][2], fmaf(hp, wH[1][2], bS[1][2]));
            float go = fmaf(in, wI[1][3], fmaf(hp, wH[1][3], bS[1][3]));
            float i_ = fmaf(tanhapx(gi), 0.5f, 0.5f);
            float f_ = fmaf(tanhapx(gf), 0.5f, 0.5f);
            float g_ = tanhapx(gg);
            float o_ = fmaf(tanhapx(go), 0.5f, 0.5f);
            c1 = fmaf(f_, c1, i_ * g_);
            acc = fmaf(o_ * tanhapx(c1), wR[1], acc);
        }

        // ---- reduce 256 channels: fixed-point warp redux + 4-warp combine ----
        int q = __float2int_rn(acc * 16777216.0f);          // 2^24
        int r = redux_s32(q);
        if (lane == 0) part[t & 1][w] = r;
        __syncthreads();
        const int* p4 = part[t & 1];
        int hi = (p4[0] + p4[1]) + (p4[2] + p4[3]);
        hp = (float)hi * 5.9604644775390625e-8f;            // 2^-24

        // ---- publish ----
        if (tid == 0) {
            if (mb_out) {
                ull v = ((ull)(unsigned)(t + 1) << 32) |
                        (ull)__float_as_uint(hp);
                *(volatile ull*)(mb_out + t) = v;
            } else {
                g_hseq[b][t] = hp;
            }
        }
    }
}

// ---------------------------------------------------------------- MLP head
// 1024 threads/block. Layer 1 (100 x 1000) uses 10 threads per output row
// (100 elements = 25 float4 loads each); partials combine through smem.
__global__ void __launch_bounds__(1024)
mlp_kernel(const float* __restrict__ W1, const float* __restrict__ b1,
           const float* __restrict__ W2, const float* __restrict__ b2,
           const float* __restrict__ W3, const float* __restrict__ b3,
           const float* __restrict__ W4, const float* __restrict__ b4,
           float* __restrict__ out)
{
    __shared__ __align__(16) float hbuf[TT];
    __shared__ float psum[100][10];
    __shared__ float a1[100], a2[100], a3[100];

    const int tid = threadIdx.x;
    const int b   = blockIdx.x;

    for (int k = tid; k < TT; k += 1024)
        hbuf[k] = g_hseq[b][k];
    __syncthreads();

    // ---- layer 1: 1000 -> 100, sigmoid; 10-way split per row ----
    if (tid < 1000) {
        const int row  = tid / 10;
        const int part = tid - row * 10;
        const float* wrow = W1 + row * 1000 + part * 100;
        const float* hrow = hbuf + part * 100;
        float s0 = 0.f, s1 = 0.f, s2 = 0.f, s3 = 0.f;
#pragma unroll
        for (int k = 0; k < 100; k += 4) {
            float4 wv = *(const float4*)(wrow + k);
            float4 hv = *(const float4*)(hrow + k);
            s0 = fmaf(wv.x, hv.x, s0);
            s1 = fmaf(wv.y, hv.y, s1);
            s2 = fmaf(wv.z, hv.z, s2);
            s3 = fmaf(wv.w, hv.w, s3);
        }
        psum[row][part] = (s0 + s1) + (s2 + s3);
    }
    __syncthreads();

    if (tid < 100) {
        float acc = b1[tid];
#pragma unroll
        for (int p = 0; p < 10; ++p)
            acc += psum[tid][p];
        a1[tid] = 1.0f / (1.0f + expf(-acc));
    }
    __syncthreads();

    // ---- layer 2: 100 -> 100, sigmoid ----
    if (tid < 100) {
        const float* wrow = W2 + tid * 100;
        float acc = b2[tid];
#pragma unroll 4
        for (int k = 0; k < 100; ++k)
            acc = fmaf(wrow[k], a1[k], acc);
        a2[tid] = 1.0f / (1.0f + expf(-acc));
    }
    __syncthreads();

    // ---- layer 3: 100 -> 100, relu ----
    if (tid < 100) {
        const float* wrow = W3 + tid * 100;
        float acc = b3[tid];
#pragma unroll 4
        for (int k = 0; k < 100; ++k)
            acc = fmaf(wrow[k], a2[k], acc);
        a3[tid] = fmaxf(acc, 0.0f);
    }
    __syncthreads();

    // ---- layer 4: 100 -> 1 ----
    if (tid == 0) {
        float acc = b4[0];
#pragma unroll 4
        for (int k = 0; k < 100; ++k)
            acc = fmaf(W4[k], a3[k], acc);
        out[b] = acc;
    }
}

extern "C" void kernel_launch(void* const* d_in, const int* in_sizes, int n_in,
                              void* d_out, int out_size)
{
    const float* x   = (const float*)d_in[0];
    const float* Wih = (const float*)d_in[1];
    const float* Whh = (const float*)d_in[2];
    const float* bih = (const float*)d_in[3];
    const float* bhh = (const float*)d_in[4];
    const float* Whr = (const float*)d_in[5];
    const float* W1  = (const float*)d_in[6];
    const float* b1  = (const float*)d_in[7];
    const float* W2  = (const float*)d_in[8];
    const float* b2  = (const float*)d_in[9];
    const float* W3  = (const float*)d_in[10];
    const float* b3  = (const float*)d_in[11];
    const float* W4  = (const float*)d_in[12];
    const float* b4  = (const float*)d_in[13];
    float* out = (float*)d_out;

    // Mailbox tags are zero on entry (globals start zeroed; reset runs last).
    lstm_layer_kernel<<<LL * BB, 128>>>(x, Wih, Whh, bih, bhh, Whr);
    mlp_kernel<<<BB, 1024>>>(W1, b1, W2, b2, W3, b3, W4, b4, out);
    reset_mbox_kernel<<<480, 256>>>();   // clean tags for the NEXT launch
}

// round 13
// speedup vs baseline: 1.6091x; 1.6091x over previous
#include <cuda_runtime.h>
#include <cstdint>
#include <math.h>

#define HH   256
#define LL   5
#define TT   1000
#define BB   128

typedef unsigned long long ull;
typedef unsigned int u32;

// Layer-4 outputs for the MLP head.
__device__ float g_hseq[BB][TT];           // 512 KB

__device__ __forceinline__ float tanhapx(float x) {
    float r;
    asm("tanh.approx.f32 %0, %1;" : "=f"(r) : "f"(x));
    return r;
}

__device__ __forceinline__ int redux_s32(int v) {
    int r;
    asm volatile("redux.sync.add.s32 %0, %1, 0xffffffff;" : "=r"(r) : "r"(v));
    return r;
}

__device__ __forceinline__ u32 smem_u32(const void* p) {
    u32 a;
    asm("{ .reg .u64 t; cvta.to.shared.u64 t, %1; cvt.u32.u64 %0, t; }"
        : "=r"(a) : "l"(p));
    return a;
}

// ---------------------------------------------------------------- LSTM pipeline
// grid = LL*BB blocks of 128 threads, clustered 5 CTAs per batch element:
// cluster rank = layer l, blockIdx.x / 5 = batch b.
//
// Cross-layer handoff via DSMEM: layer l stores the tagged {t+1, h} word
// directly into layer (l+1)'s OWN smem inbox (mapa'd once, one relaxed
// cluster-scope 8B store per step, fire-and-forget). The consumer polls its
// LOCAL smem (LDS ~29cyc) instead of an L2 line (~250+cyc round trip).
// Inbox covers all TT steps (8KB smem) -> no ring, no backpressure.
// Intra-block step math is byte-identical to the best-measured round (R4).
__global__ void __launch_bounds__(128) __cluster_dims__(LL, 1, 1)
lstm_layer_kernel(const float* __restrict__ x,
                  const float* __restrict__ Wih,
                  const float* __restrict__ Whh,
                  const float* __restrict__ bih,
                  const float* __restrict__ bhh,
                  const float* __restrict__ Whr)
{
    __shared__ __align__(16) ull   inbox[TT];    // 8 KB, written by layer l-1
    __shared__ __align__(16) float xbuf[TT];     // 4 KB, used by layer 0 only
    __shared__ __align__(16) int   part[2][4];   // [t&1][warp]

    const int tid  = threadIdx.x;
    u32 rank;
    asm("mov.u32 %0, %%cluster_ctarank;" : "=r"(rank));
    const int l    = (int)rank;            // layer
    const int b    = blockIdx.x / LL;      // batch element
    const int w    = tid >> 5;             // warp in block (0..3)
    const int lane = tid & 31;

    // ---- per-thread weights: 2 channels x 4 gates ----
    // gate order i,f,g,o; sigmoid(x)=0.5*tanh(0.5x)+0.5 with 0.5 folded in.
    float wI[2][4], wH[2][4], bS[2][4], wR[2];
#pragma unroll
    for (int ch = 0; ch < 2; ++ch) {
        int h = tid + ch * 128;
#pragma unroll
        for (int g = 0; g < 4; ++g) {
            int idx = l * 1024 + g * 256 + h;
            float s = (g == 2) ? 1.0f : 0.5f;
            wI[ch][g] = Wih[idx] * s;
            wH[ch][g] = Whh[idx] * s;
            bS[ch][g] = (bih[idx] + bhh[idx]) * s;
        }
        wR[ch] = Whr[l * 256 + h];
    }

    // ---- init: zero my inbox tags; layer 0 stages x ----
    for (int k = tid; k < TT; k += 128)
        inbox[k] = 0ull;
    if (l == 0) {
        for (int k = tid; k < TT; k += 128)
            xbuf[k] = x[b * TT + k];
    }
    __syncthreads();

    // Cluster barrier: all inboxes zeroed before any producer may store.
    asm volatile("barrier.cluster.arrive.aligned;" ::: "memory");
    asm volatile("barrier.cluster.wait.aligned;"   ::: "memory");

    // Map my inbox base address into the NEXT rank's smem window (producer side).
    const u32 my_inbox = smem_u32(inbox);
    u32 peer_inbox = 0;
    if (l < LL - 1) {
        asm("mapa.shared::cluster.u32 %0, %1, %2;"
            : "=r"(peer_inbox) : "r"(my_inbox), "r"(l + 1));
    }

    float c0 = 0.0f, c1 = 0.0f;
    float hp = 0.0f;
    float xin = (l == 0) ? xbuf[0] : 0.0f;

    for (int t = 0; t < TT; ++t) {
        // ---- obtain input ----
        float in;
        if (l == 0) {
            in = xin;
            if (t + 1 < TT) xin = xbuf[t + 1];
        } else {
            const u32 slot = my_inbox + (u32)(t * 8);
            const unsigned want = (unsigned)(t + 1);
            ull v;
            asm volatile("ld.volatile.shared.b64 %0, [%1];" : "=l"(v) : "r"(slot));
            while ((unsigned)(v >> 32) != want) {
                asm volatile("ld.volatile.shared.b64 %0, [%1];" : "=l"(v) : "r"(slot));
            }
            in = __uint_as_float((unsigned)v);
        }

        // ---- two channels of the LSTM cell (f32) ----
        float acc;
        {   // channel 0
            float gi = fmaf(in, wI[0][0], fmaf(hp, wH[0][0], bS[0][0]));
            float gf = fmaf(in, wI[0][1], fmaf(hp, wH[0][1], bS[0][1]));
            float gg = fmaf(in, wI[0][2], fmaf(hp, wH[0][2], bS[0][2]));
            float go = fmaf(in, wI[0][3], fmaf(hp, wH[0][3], bS[0][3]));
            float i_ = fmaf(tanhapx(gi), 0.5f, 0.5f);
            float f_ = fmaf(tanhapx(gf), 0.5f, 0.5f);
            float g_ = tanhapx(gg);
            float o_ = fmaf(tanhapx(go), 0.5f, 0.5f);
            c0 = fmaf(f_, c0, i_ * g_);
            acc = (o_ * tanhapx(c0)) * wR[0];
        }
        {   // channel 1
            float gi = fmaf(in, wI[1][0], fmaf(hp, wH[1][0], bS[1][0]));
            float gf = fmaf(in, wI[1][1], fmaf(hp, wH[1][1], bS[1][1]));
            float gg = fmaf(in, wI[1][2], fmaf(hp, wH[1][2], bS[1][2]));
            float go = fmaf(in, wI[1][3], fmaf(hp, wH[1][3], bS[1][3]));
            float i_ = fmaf(tanhapx(gi), 0.5f, 0.5f);
            float f_ = fmaf(tanhapx(gf), 0.5f, 0.5f);
            float g_ = tanhapx(gg);
            float o_ = fmaf(tanhapx(go), 0.5f, 0.5f);
            c1 = fmaf(f_, c1, i_ * g_);
            acc = fmaf(o_ * tanhapx(c1), wR[1], acc);
        }

        // ---- reduce 256 channels: fixed-point warp redux + 4-warp combine ----
        int q = __float2int_rn(acc * 16777216.0f);          // 2^24
        int r = redux_s32(q);
        if (lane == 0) part[t & 1][w] = r;
        __syncthreads();
        const int* p4 = part[t & 1];
        int hi = (p4[0] + p4[1]) + (p4[2] + p4[3]);
        hp = (float)hi * 5.9604644775390625e-8f;            // 2^-24

        // ---- publish: one remote 8B store into the next layer's inbox ----
        if (tid == 0) {
            if (l < LL - 1) {
                ull v = ((ull)(unsigned)(t + 1) << 32) |
                        (ull)__float_as_uint(hp);
                asm volatile("st.relaxed.cluster.shared::cluster.b64 [%0], %1;"
                             :: "r"(peer_inbox + (u32)(t * 8)), "l"(v)
                             : "memory");
            } else {
                g_hseq[b][t] = hp;
            }
        }
    }

    // Keep all CTAs of the cluster resident until every handoff has landed.
    asm volatile("barrier.cluster.arrive.aligned;" ::: "memory");
    asm volatile("barrier.cluster.wait.aligned;"   ::: "memory");
}

// ---------------------------------------------------------------- MLP head
// 1024 threads/block. Layer 1 (100 x 1000) uses 10 threads per output row
// (100 elements = 25 float4 loads each); partials combine through smem.
__global__ void __launch_bounds__(1024)
mlp_kernel(const float* __restrict__ W1, const float* __restrict__ b1,
           const float* __restrict__ W2, const float* __restrict__ b2,
           const float* __restrict__ W3, const float* __restrict__ b3,
           const float* __restrict__ W4, const float* __restrict__ b4,
           float* __restrict__ out)
{
    __shared__ __align__(16) float hbuf[TT];
    __shared__ float psum[100][10];
    __shared__ float a1[100], a2[100], a3[100];

    const int tid = threadIdx.x;
    const int b   = blockIdx.x;

    for (int k = tid; k < TT; k += 1024)
        hbuf[k] = g_hseq[b][k];
    __syncthreads();

    // ---- layer 1: 1000 -> 100, sigmoid; 10-way split per row ----
    if (tid < 1000) {
        const int row  = tid / 10;
        const int part = tid - row * 10;
        const float* wrow = W1 + row * 1000 + part * 100;
        const float* hrow = hbuf + part * 100;
        float s0 = 0.f, s1 = 0.f, s2 = 0.f, s3 = 0.f;
#pragma unroll
        for (int k = 0; k < 100; k += 4) {
            float4 wv = *(const float4*)(wrow + k);
            float4 hv = *(const float4*)(hrow + k);
            s0 = fmaf(wv.x, hv.x, s0);
            s1 = fmaf(wv.y, hv.y, s1);
            s2 = fmaf(wv.z, hv.z, s2);
            s3 = fmaf(wv.w, hv.w, s3);
        }
        psum[row][part] = (s0 + s1) + (s2 + s3);
    }
    __syncthreads();

    if (tid < 100) {
        float acc = b1[tid];
#pragma unroll
        for (int p = 0; p < 10; ++p)
            acc += psum[tid][p];
        a1[tid] = 1.0f / (1.0f + expf(-acc));
    }
    __syncthreads();

    // ---- layer 2: 100 -> 100, sigmoid ----
    if (tid < 100) {
        const float* wrow = W2 + tid * 100;
        float acc = b2[tid];
#pragma unroll 4
        for (int k = 0; k < 100; ++k)
            acc = fmaf(wrow[k], a1[k], acc);
        a2[tid] = 1.0f / (1.0f + expf(-acc));
    }
    __syncthreads();

    // ---- layer 3: 100 -> 100, relu ----
    if (tid < 100) {
        const float* wrow = W3 + tid * 100;
        float acc = b3[tid];
#pragma unroll 4
        for (int k = 0; k < 100; ++k)
            acc = fmaf(wrow[k], a2[k], acc);
        a3[tid] = fmaxf(acc, 0.0f);
    }
    __syncthreads();

    // ---- layer 4: 100 -> 1 ----
    if (tid == 0) {
        float acc = b4[0];
#pragma unroll 4
        for (int k = 0; k < 100; ++k)
            acc = fmaf(W4[k], a3[k], acc);
        out[b] = acc;
    }
}

extern "C" void kernel_launch(void* const* d_in, const int* in_sizes, int n_in,
                              void* d_out, int out_size)
{
    const float* x   = (const float*)d_in[0];
    const float* Wih = (const float*)d_in[1];
    const float* Whh = (const float*)d_in[2];
    const float* bih = (const float*)d_in[3];
    const float* bhh = (const float*)d_in[4];
    const float* Whr = (const float*)d_in[5];
    const float* W1  = (const float*)d_in[6];
    const float* b1  = (const float*)d_in[7];
    const float* W2  = (const float*)d_in[8];
    const float* b2  = (const float*)d_in[9];
    const float* W3  = (const float*)d_in[10];
    const float* b3  = (const float*)d_in[11];
    const float* W4  = (const float*)d_in[12];
    const float* b4  = (const float*)d_in[13];
    float* out = (float*)d_out;

    lstm_layer_kernel<<<LL * BB, 128>>>(x, Wih, Whh, bih, bhh, Whr);
    mlp_kernel<<<BB, 1024>>>(W1, b1, W2, b2, W3, b3, W4, b4, out);
}

// round 14
// speedup vs baseline: 1.6401x; 1.0193x over previous
#include <cuda_runtime.h>
#include <cstdint>
#include <math.h>

#define HH   256
#define LL   5
#define TT   1000
#define BB   128

typedef unsigned long long ull;
typedef unsigned int u32;

// Layer-4 outputs for the MLP head.
__device__ float g_hseq[BB][TT];           // 512 KB

__device__ __forceinline__ float tanhapx(float x) {
    float r;
    asm("tanh.approx.f32 %0, %1;" : "=f"(r) : "f"(x));
    return r;
}

__device__ __forceinline__ int redux_s32(int v) {
    int r;
    asm volatile("redux.sync.add.s32 %0, %1, 0xffffffff;" : "=r"(r) : "r"(v));
    return r;
}

__device__ __forceinline__ u32 smem_u32(const void* p) {
    u32 a;
    asm("{ .reg .u64 t; cvta.to.shared.u64 t, %1; cvt.u32.u64 %0, t; }"
        : "=r"(a) : "l"(p));
    return a;
}

// ---------------------------------------------------------------- LSTM pipeline
// grid = LL*BB blocks of 128 threads, clustered 5 CTAs per batch element:
// cluster rank = layer l, blockIdx.x / 5 = batch b.
//
// Cross-layer handoff via DSMEM (unchanged from the 340us round): producer
// stores the tagged {t+1, h} word into the next layer's smem inbox; consumer
// polls its LOCAL smem.
//
// ONE change vs 340us round: magic-number fixed point. Per-lane partial acc
// -> s32 via float_as_int(fma(acc, 2^20, MAGIC)) - MBITS (no F2I). The 4-warp
// sum s is consumed as hp_raw = int_as_float(s + MBITS) = MAGIC + (float)s
// exactly (|s| < 2^22), with wH pre-scaled by 2^-20 and bias shifted by
// -MAGIC*wH' so gates use hp_raw directly (no I2F). Cross-layer h value is
// reconstructed only on the publish lane.
__global__ void __launch_bounds__(128) __cluster_dims__(LL, 1, 1)
lstm_layer_kernel(const float* __restrict__ x,
                  const float* __restrict__ Wih,
                  const float* __restrict__ Whh,
                  const float* __restrict__ bih,
                  const float* __restrict__ bhh,
                  const float* __restrict__ Whr)
{
    __shared__ __align__(16) ull   inbox[TT];    // 8 KB, written by layer l-1
    __shared__ __align__(16) float xbuf[TT];     // 4 KB, used by layer 0 only
    __shared__ __align__(16) int   part[2][4];   // [t&1][warp]

    const int tid  = threadIdx.x;
    u32 rank;
    asm("mov.u32 %0, %%cluster_ctarank;" : "=r"(rank));
    const int l    = (int)rank;            // layer
    const int b    = blockIdx.x / LL;      // batch element
    const int w    = tid >> 5;             // warp in block (0..3)
    const int lane = tid & 31;

    const float MAGIC  = 12582912.0f;          // 1.5 * 2^23
    const int   MBITS  = 0x4B400000;           // bit pattern of MAGIC
    const float SCALE  = 1048576.0f;           // 2^20
    const float INVSCL = 9.5367431640625e-7f;  // 2^-20

    // ---- per-thread weights: 2 channels x 4 gates ----
    // gate order i,f,g,o; sigmoid(x)=0.5*tanh(0.5x)+0.5 with 0.5 folded in.
    // wH additionally pre-scaled by 2^-20, bias shifted by -MAGIC*wH' so the
    // raw (magic-biased) hp feeds the gate FMA directly.
    float wI[2][4], wH[2][4], bS[2][4], wR[2];
#pragma unroll
    for (int ch = 0; ch < 2; ++ch) {
        int h = tid + ch * 128;
#pragma unroll
        for (int g = 0; g < 4; ++g) {
            int idx = l * 1024 + g * 256 + h;
            float s = (g == 2) ? 1.0f : 0.5f;
            float wh = Whh[idx] * s * INVSCL;
            wI[ch][g] = Wih[idx] * s;
            wH[ch][g] = wh;
            bS[ch][g] = (bih[idx] + bhh[idx]) * s - MAGIC * wh;
        }
        wR[ch] = Whr[l * 256 + h];
    }

    // ---- init: zero my inbox tags; layer 0 stages x ----
    for (int k = tid; k < TT; k += 128)
        inbox[k] = 0ull;
    if (l == 0) {
        for (int k = tid; k < TT; k += 128)
            xbuf[k] = x[b * TT + k];
    }
    __syncthreads();

    // Cluster barrier: all inboxes zeroed before any producer may store.
    asm volatile("barrier.cluster.arrive.aligned;" ::: "memory");
    asm volatile("barrier.cluster.wait.aligned;"   ::: "memory");

    // Map my inbox base address into the NEXT rank's smem window (producer side).
    const u32 my_inbox = smem_u32(inbox);
    u32 peer_inbox = 0;
    if (l < LL - 1) {
        asm("mapa.shared::cluster.u32 %0, %1, %2;"
            : "=r"(peer_inbox) : "r"(my_inbox), "r"(l + 1));
    }

    float c0 = 0.0f, c1 = 0.0f;
    float hp_raw = MAGIC;                  // fixed-point s=0 at t=0
    float xin = (l == 0) ? xbuf[0] : 0.0f;

    for (int t = 0; t < TT; ++t) {
        // ---- obtain input ----
        float in;
        if (l == 0) {
            in = xin;
            if (t + 1 < TT) xin = xbuf[t + 1];
        } else {
            const u32 slot = my_inbox + (u32)(t * 8);
            const unsigned want = (unsigned)(t + 1);
            ull v;
            asm volatile("ld.volatile.shared.b64 %0, [%1];" : "=l"(v) : "r"(slot));
            while ((unsigned)(v >> 32) != want) {
                asm volatile("ld.volatile.shared.b64 %0, [%1];" : "=l"(v) : "r"(slot));
            }
            in = __uint_as_float((unsigned)v);
        }

        // ---- two channels of the LSTM cell (f32, hp in magic-raw form) ----
        float acc;
        {   // channel 0
            float gi = fmaf(hp_raw, wH[0][0], fmaf(in, wI[0][0], bS[0][0]));
            float gf = fmaf(hp_raw, wH[0][1], fmaf(in, wI[0][1], bS[0][1]));
            float gg = fmaf(hp_raw, wH[0][2], fmaf(in, wI[0][2], bS[0][2]));
            float go = fmaf(hp_raw, wH[0][3], fmaf(in, wI[0][3], bS[0][3]));
            float i_ = fmaf(tanhapx(gi), 0.5f, 0.5f);
            float f_ = fmaf(tanhapx(gf), 0.5f, 0.5f);
            float g_ = tanhapx(gg);
            float o_ = fmaf(tanhapx(go), 0.5f, 0.5f);
            c0 = fmaf(f_, c0, i_ * g_);
            acc = (o_ * tanhapx(c0)) * wR[0];
        }
        {   // channel 1
            float gi = fmaf(hp_raw, wH[1][0], fmaf(in, wI[1][0], bS[1][0]));
            float gf = fmaf(hp_raw, wH[1][1], fmaf(in, wI[1][1], bS[1][1]));
            float gg = fmaf(hp_raw, wH[1][2], fmaf(in, wI[1][2], bS[1][2]));
            float go = fmaf(hp_raw, wH[1][3], fmaf(in, wI[1][3], bS[1][3]));
            float i_ = fmaf(tanhapx(gi), 0.5f, 0.5f);
            float f_ = fmaf(tanhapx(gf), 0.5f, 0.5f);
            float g_ = tanhapx(gg);
            float o_ = fmaf(tanhapx(go), 0.5f, 0.5f);
            c1 = fmaf(f_, c1, i_ * g_);
            acc = fmaf(o_ * tanhapx(c1), wR[1], acc);
        }

        // ---- fixed-point (magic, no F2I) + warp redux + 4-warp combine ----
        int q = __float_as_int(fmaf(acc, SCALE, MAGIC)) - MBITS;
        int r = redux_s32(q);
        if (lane == 0) part[t & 1][w] = r;
        __syncthreads();
        const int* p4 = part[t & 1];
        int s = (p4[0] + p4[1]) + (p4[2] + p4[3]);
        hp_raw = __int_as_float(s + MBITS);        // = MAGIC + (float)s, no I2F

        // ---- publish: one remote 8B store into the next layer's inbox ----
        if (tid == 0) {
            float hval = (hp_raw - MAGIC) * INVSCL;
            if (l < LL - 1) {
                ull v = ((ull)(unsigned)(t + 1) << 32) |
                        (ull)__float_as_uint(hval);
                asm volatile("st.relaxed.cluster.shared::cluster.b64 [%0], %1;"
                             :: "r"(peer_inbox + (u32)(t * 8)), "l"(v)
                             : "memory");
            } else {
                g_hseq[b][t] = hval;
            }
        }
    }

    // Keep all CTAs of the cluster resident until every handoff has landed.
    asm volatile("barrier.cluster.arrive.aligned;" ::: "memory");
    asm volatile("barrier.cluster.wait.aligned;"   ::: "memory");
}

// ---------------------------------------------------------------- MLP head
// 1024 threads/block. Layer 1 (100 x 1000) uses 10 threads per output row
// (100 elements = 25 float4 loads each); partials combine through smem.
__global__ void __launch_bounds__(1024)
mlp_kernel(const float* __restrict__ W1, const float* __restrict__ b1,
           const float* __restrict__ W2, const float* __restrict__ b2,
           const float* __restrict__ W3, const float* __restrict__ b3,
           const float* __restrict__ W4, const float* __restrict__ b4,
           float* __restrict__ out)
{
    __shared__ __align__(16) float hbuf[TT];
    __shared__ float psum[100][10];
    __shared__ float a1[100], a2[100], a3[100];

    const int tid = threadIdx.x;
    const int b   = blockIdx.x;

    for (int k = tid; k < TT; k += 1024)
        hbuf[k] = g_hseq[b][k];
    __syncthreads();

    // ---- layer 1: 1000 -> 100, sigmoid; 10-way split per row ----
    if (tid < 1000) {
        const int row  = tid / 10;
        const int part = tid - row * 10;
        const float* wrow = W1 + row * 1000 + part * 100;
        const float* hrow = hbuf + part * 100;
        float s0 = 0.f, s1 = 0.f, s2 = 0.f, s3 = 0.f;
#pragma unroll
        for (int k = 0; k < 100; k += 4) {
            float4 wv = *(const float4*)(wrow + k);
            float4 hv = *(const float4*)(hrow + k);
            s0 = fmaf(wv.x, hv.x, s0);
            s1 = fmaf(wv.y, hv.y, s1);
            s2 = fmaf(wv.z, hv.z, s2);
            s3 = fmaf(wv.w, hv.w, s3);
        }
        psum[row][part] = (s0 + s1) + (s2 + s3);
    }
    __syncthreads();

    if (tid < 100) {
        float acc = b1[tid];
#pragma unroll
        for (int p = 0; p < 10; ++p)
            acc += psum[tid][p];
        a1[tid] = 1.0f / (1.0f + expf(-acc));
    }
    __syncthreads();

    // ---- layer 2: 100 -> 100, sigmoid ----
    if (tid < 100) {
        const float* wrow = W2 + tid * 100;
        float acc = b2[tid];
#pragma unroll 4
        for (int k = 0; k < 100; ++k)
            acc = fmaf(wrow[k], a1[k], acc);
        a2[tid] = 1.0f / (1.0f + expf(-acc));
    }
    __syncthreads();

    // ---- layer 3: 100 -> 100, relu ----
    if (tid < 100) {
        const float* wrow = W3 + tid * 100;
        float acc = b3[tid];
#pragma unroll 4
        for (int k = 0; k < 100; ++k)
            acc = fmaf(wrow[k], a2[k], acc);
        a3[tid] = fmaxf(acc, 0.0f);
    }
    __syncthreads();

    // ---- layer 4: 100 -> 1 ----
    if (tid == 0) {
        float acc = b4[0];
#pragma unroll 4
        for (int k = 0; k < 100; ++k)
            acc = fmaf(W4[k], a3[k], acc);
        out[b] = acc;
    }
}

extern "C" void kernel_launch(void* const* d_in, const int* in_sizes, int n_in,
                              void* d_out, int out_size)
{
    const float* x   = (const float*)d_in[0];
    const float* Wih = (const float*)d_in[1];
    const float* Whh = (const float*)d_in[2];
    const float* bih = (const float*)d_in[3];
    const float* bhh = (const float*)d_in[4];
    const float* Whr = (const float*)d_in[5];
    const float* W1  = (const float*)d_in[6];
    const float* b1  = (const float*)d_in[7];
    const float* W2  = (const float*)d_in[8];
    const float* b2  = (const float*)d_in[9];
    const float* W3  = (const float*)d_in[10];
    const float* b3  = (const float*)d_in[11];
    const float* W4  = (const float*)d_in[12];
    const float* b4  = (const float*)d_in[13];
    float* out = (float*)d_out;

    lstm_layer_kernel<<<LL * BB, 128>>>(x, Wih, Whh, bih, bhh, Whr);
    mlp_kernel<<<BB, 1024>>>(W1, b1, W2, b2, W3, b3, W4, b4, out);
}